// round 9
// baseline (speedup 1.0000x reference)
#include <cuda_runtime.h>
#include <cuda_bf16.h>
#include <math.h>
#include <stdint.h>

// ---------------------------------------------------------------------------
// LINKX forward, restructured DAG:
//   z5 = cat@ww1 + bw1 = hb@(wx2@W5t) + h2b@(wa2@W5b) + b5'   (linear algebra)
// so the K=256 concat GEMM disappears into two fused N=256 K=128 GEMMs.
//   main: compose(U,V,b5') -> prep -> G1(hb) -> [G2|G5a fused]
//   side: bin/count/scan/fill/gather(aggb) -> G3(h2b)
//   join: [G4|G5b fused] -> G6 (combine folded into staging)
// GEMMs: mma.sync bf16 2-term split (hh+hl+lh), 128x128 tiles, 8 warps.
// ---------------------------------------------------------------------------

#define NMAX   100000
#define EMAX   1600000
#define HID    128
#define INDIM  256

// fp32 buffers
__device__ float g_hx[(size_t)NMAX * HID];
__device__ float g_ha[(size_t)NMAX * HID];
__device__ float g_z5[(size_t)NMAX * HID];
__device__ float g_uv[2 * 128 * 128];          // U | V composites
__device__ float g_b5[128];
// bf16-split activation planes (hi plane then lo plane)
__device__ __align__(16) __nv_bfloat16 g_hb[2 * (size_t)NMAX * HID];
__device__ __align__(16) __nv_bfloat16 g_h2b[2 * (size_t)NMAX * HID];
__device__ __align__(16) __nv_bfloat16 g_aggb[2 * (size_t)NMAX * HID];
__device__ __align__(16) __nv_bfloat16 g_wt[229376];
// binning scratch
__device__ int g_cnt[NMAX];
__device__ int g_cur[NMAX];
__device__ int g_off[NMAX + 1];
__device__ int g_bins[EMAX];

// ---- helpers --------------------------------------------------------------
__device__ __forceinline__ uint32_t smem_u32(const void* p) {
    uint32_t a;
    asm("{ .reg .u64 t; cvta.to.shared.u64 t, %1; cvt.u32.u64 %0, t; }"
        : "=r"(a) : "l"(p));
    return a;
}

#define LDSM_X4(r0, r1, r2, r3, addr) \
    asm volatile("ldmatrix.sync.aligned.m8n8.x4.shared.b16 {%0,%1,%2,%3}, [%4];" \
                 : "=r"(r0), "=r"(r1), "=r"(r2), "=r"(r3) : "r"(addr))

#define MMA_BF16(acc, a, b0v, b1v) \
    asm volatile("mma.sync.aligned.m16n8k16.row.col.f32.bf16.bf16.f32 " \
                 "{%0,%1,%2,%3}, {%4,%5,%6,%7}, {%8,%9}, {%0,%1,%2,%3};" \
                 : "+f"((acc)[0]), "+f"((acc)[1]), "+f"((acc)[2]), "+f"((acc)[3]) \
                 : "r"((a)[0]), "r"((a)[1]), "r"((a)[2]), "r"((a)[3]), \
                   "r"(b0v), "r"(b1v))

__device__ __forceinline__ uint32_t pack_bf2(__nv_bfloat16 lo, __nv_bfloat16 hi) {
    __nv_bfloat162 p;
    p.x = lo; p.y = hi;
    return *reinterpret_cast<uint32_t*>(&p);
}

__device__ __forceinline__ void bsplit(float x, __nv_bfloat16& h, __nv_bfloat16& l) {
    h = __float2bfloat16(x);
    l = __float2bfloat16(x - __bfloat162float(h));
}

// ---------------------------------------------------------------------------
// Binning aggregation (proven)
// ---------------------------------------------------------------------------
__global__ void zero_cnt(int* cnt, int* cur, int M) {
    int i = blockIdx.x * blockDim.x + threadIdx.x;
    if (i < M) { cnt[i] = 0; cur[i] = 0; }
}

__global__ void count_kernel(const int* __restrict__ ei, int* __restrict__ cnt, int E) {
    int i = blockIdx.x * blockDim.x + threadIdx.x;
    int stride = gridDim.x * blockDim.x;
    for (int e = i; e < E; e += stride)
        atomicAdd(&cnt[__ldg(&ei[E + e])], 1);
}

__global__ void scan_kernel(const int* __restrict__ cnt, int* __restrict__ off, int M) {
    __shared__ int part[1024];
    const int t = threadIdx.x;
    const int chunk = (M + 1023) >> 10;
    const int beg = t * chunk;
    const int end = min(beg + chunk, M);
    int s = 0;
    for (int i = beg; i < end; ++i) s += cnt[i];
    part[t] = s;
    __syncthreads();
    for (int d = 1; d < 1024; d <<= 1) {
        int v = (t >= d) ? part[t - d] : 0;
        __syncthreads();
        part[t] += v;
        __syncthreads();
    }
    int run = (t == 0) ? 0 : part[t - 1];
    for (int i = beg; i < end; ++i) { off[i] = run; run += cnt[i]; }
    if (t == 1023) off[M] = run;
}

__global__ void fill_kernel(const int* __restrict__ ei,
                            const int* __restrict__ off,
                            int* __restrict__ cur,
                            int* __restrict__ bins, int E) {
    int i = blockIdx.x * blockDim.x + threadIdx.x;
    int stride = gridDim.x * blockDim.x;
    for (int e = i; e < E; e += stride) {
        int src = __ldg(&ei[e]);
        int dst = __ldg(&ei[E + e]);
        int slot = atomicAdd(&cur[dst], 1);
        bins[off[dst] + slot] = src;
    }
}

__global__ void gather_kernel(const int* __restrict__ off,
                              const int* __restrict__ bins,
                              const float* __restrict__ emb,
                              __nv_bfloat16* __restrict__ aggh,
                              __nv_bfloat16* __restrict__ aggl, int M) {
    int w    = (blockIdx.x * blockDim.x + threadIdx.x) >> 5;
    int lane = threadIdx.x & 31;
    if (w >= M) return;
    int beg = __ldg(&off[w]);
    int end = __ldg(&off[w + 1]);
    float4 acc = make_float4(0.f, 0.f, 0.f, 0.f);
    int e = beg;
    for (; e + 1 < end; e += 2) {
        int s0 = __ldg(&bins[e]);
        int s1 = __ldg(&bins[e + 1]);
        float4 v0 = __ldg((const float4*)(emb + (size_t)s0 * HID + lane * 4));
        float4 v1 = __ldg((const float4*)(emb + (size_t)s1 * HID + lane * 4));
        acc.x += v0.x + v1.x; acc.y += v0.y + v1.y;
        acc.z += v0.z + v1.z; acc.w += v0.w + v1.w;
    }
    if (e < end) {
        int s0 = __ldg(&bins[e]);
        float4 v0 = __ldg((const float4*)(emb + (size_t)s0 * HID + lane * 4));
        acc.x += v0.x; acc.y += v0.y; acc.z += v0.z; acc.w += v0.w;
    }
    float inv = 1.0f / (float)max(end - beg, 1);
    __nv_bfloat16 h0,h1,h2,h3, l0,l1,l2,l3;
    bsplit(acc.x * inv, h0, l0);
    bsplit(acc.y * inv, h1, l1);
    bsplit(acc.z * inv, h2, l2);
    bsplit(acc.w * inv, h3, l3);
    size_t o = (size_t)w * HID + lane * 4;
    *(uint2*)(aggh + o) = make_uint2(pack_bf2(h0, h1), pack_bf2(h2, h3));
    *(uint2*)(aggl + o) = make_uint2(pack_bf2(l0, l1), pack_bf2(l2, l3));
}

// ---------------------------------------------------------------------------
// Composite weights: U = wx2@W5t, V = wa2@W5b  (W5t/W5b halves of ww1[256,128])
__global__ void compose_kernel(const float* __restrict__ wx2,
                               const float* __restrict__ wa2,
                               const float* __restrict__ ww1,
                               float* __restrict__ UV) {
    int mat = blockIdx.y;               // 0: U, 1: V
    int i = blockIdx.x;
    int j = threadIdx.x;
    const float* A  = mat ? wa2 : wx2;
    const float* Wp = ww1 + (mat ? 128 * 128 : 0);
    float s = 0.f;
#pragma unroll 8
    for (int k = 0; k < 128; ++k)
        s = fmaf(__ldg(&A[i * 128 + k]), __ldg(&Wp[k * 128 + j]), s);
    UV[mat * 16384 + i * 128 + j] = s;
}

// b5'[j] = bw1[j] + bx2@W5t[:,j] + ba2@W5b[:,j]
__global__ void bias5_kernel(const float* __restrict__ bx2,
                             const float* __restrict__ ba2,
                             const float* __restrict__ bw1,
                             const float* __restrict__ ww1,
                             float* __restrict__ b5) {
    int j = threadIdx.x;
    float s = bw1[j];
    for (int k = 0; k < 128; ++k) {
        s = fmaf(bx2[k], ww1[k * 128 + j], s);
        s = fmaf(ba2[k], ww1[(128 + k) * 128 + j], s);
    }
    b5[j] = s;
}

// ---------------------------------------------------------------------------
// Weight prep: split+transpose into B^T planes.
// g_wt layout (elements):
//   [0]      W1  (wx1, N=128, K=256):  hi 32768 | lo 32768
//   [65536]  WB2 ([wx2|U], N=256, K=128): hi 32768 | lo 32768
//   [131072] W3  (wa1, N=128, K=128): hi 16384 | lo 16384
//   [163840] WB4 ([wa2|V], N=256, K=128): hi 32768 | lo 32768
__global__ void prep_all2(const float* __restrict__ wx1,
                          const float* __restrict__ wx2,
                          const float* __restrict__ wa1,
                          const float* __restrict__ wa2,
                          const float* __restrict__ UV,
                          __nv_bfloat16* __restrict__ WT) {
    int t = blockIdx.x * blockDim.x + threadIdx.x;
    float v;
    __nv_bfloat16 *dh, *dl;
    if (t < 32768) {                       // wx1 [256,128] -> [128][256]
        int k = t >> 7, n = t & 127;
        v = wx1[t];
        dh = WT + (size_t)n * 256 + k;
        dl = dh + 32768;
    } else if (t < 65536) {                // [wx2|U] -> [256][128]
        int u = t - 32768;
        int k = u >> 8, n = u & 255;
        v = (n < 128) ? wx2[k * 128 + n] : UV[k * 128 + (n - 128)];
        dh = WT + 65536 + (size_t)n * 128 + k;
        dl = dh + 32768;
    } else if (t < 81920) {                // wa1 -> [128][128]
        int u = t - 65536;
        int k = u >> 7, n = u & 127;
        v = wa1[u];
        dh = WT + 131072 + (size_t)n * 128 + k;
        dl = dh + 16384;
    } else if (t < 114688) {               // [wa2|V] -> [256][128]
        int u = t - 81920;
        int k = u >> 8, n = u & 255;
        v = (n < 128) ? wa2[k * 128 + n] : UV[16384 + k * 128 + (n - 128)];
        dh = WT + 163840 + (size_t)n * 128 + k;
        dl = dh + 32768;
    } else return;
    __nv_bfloat16 h, l;
    bsplit(v, h, l);
    *dh = h;
    *dl = l;
}

// ---------------------------------------------------------------------------
// Shared MMA mainloop. smem S: AH(0) AL(3072) BH(6144) BL(9216), elems.
// A_MODE 0: A from fp32 (split in staging); 1: A from pre-split planes.
// B planes already offset to the CTA's 128-row block of B^T.
template <int K_DIM, int A_MODE>
__device__ __forceinline__ void mma_mainloop(
    const float* __restrict__ Af,
    const __nv_bfloat16* __restrict__ Ah, const __nv_bfloat16* __restrict__ Al,
    const __nv_bfloat16* __restrict__ Bh, const __nv_bfloat16* __restrict__ Bl,
    int M, int bm, __nv_bfloat16* S, uint32_t uS, float acc[2][8][4]) {
    const int tid  = threadIdx.x;
    const int wid  = tid >> 5;
    const int lane = tid & 31;
    const int wm   = wid >> 1;
    const int wn   = wid & 1;
    const int a_r0 = (lane & 7) + ((lane >> 3) & 1) * 8;
    const int a_ch = lane >> 4;
    const int b_n0 = (lane & 7) + ((lane >> 4) & 1) * 8;
    const int b_ch = (lane >> 3) & 1;
    const int srow = tid >> 1;
    const int sh   = tid & 1;

    for (int c = 0; c < K_DIM / 16; ++c) {
        const int k0 = c * 16;
        if (A_MODE == 0) {
            int gr = bm + srow;
            float4 v0 = make_float4(0.f, 0.f, 0.f, 0.f), v1 = v0;
            if (gr < M) {
                const float* p = Af + (size_t)gr * K_DIM + k0 + sh * 8;
                v0 = *(const float4*)p;
                v1 = *(const float4*)(p + 4);
            }
            __nv_bfloat16 h0,h1,h2,h3,h4,h5,h6,h7, l0,l1,l2,l3,l4,l5,l6,l7;
            bsplit(v0.x, h0, l0); bsplit(v0.y, h1, l1);
            bsplit(v0.z, h2, l2); bsplit(v0.w, h3, l3);
            bsplit(v1.x, h4, l4); bsplit(v1.y, h5, l5);
            bsplit(v1.z, h6, l6); bsplit(v1.w, h7, l7);
            *(uint4*)&S[srow * 24 + sh * 8] =
                make_uint4(pack_bf2(h0,h1), pack_bf2(h2,h3),
                           pack_bf2(h4,h5), pack_bf2(h6,h7));
            *(uint4*)&S[3072 + srow * 24 + sh * 8] =
                make_uint4(pack_bf2(l0,l1), pack_bf2(l2,l3),
                           pack_bf2(l4,l5), pack_bf2(l6,l7));
        } else {
            int gr = min(bm + srow, M - 1);
            *(uint4*)&S[srow * 24 + sh * 8] =
                *(const uint4*)&Ah[(size_t)gr * K_DIM + k0 + sh * 8];
            *(uint4*)&S[3072 + srow * 24 + sh * 8] =
                *(const uint4*)&Al[(size_t)gr * K_DIM + k0 + sh * 8];
        }
        *(uint4*)&S[6144 + srow * 24 + sh * 8] =
            *(const uint4*)&Bh[(size_t)srow * K_DIM + k0 + sh * 8];
        *(uint4*)&S[9216 + srow * 24 + sh * 8] =
            *(const uint4*)&Bl[(size_t)srow * K_DIM + k0 + sh * 8];
        __syncthreads();

        uint32_t ah[2][4], al[2][4];
#pragma unroll
        for (int mt = 0; mt < 2; ++mt) {
            int arow = wm * 32 + mt * 16 + a_r0;
            LDSM_X4(ah[mt][0], ah[mt][1], ah[mt][2], ah[mt][3],
                    uS + arow * 48 + a_ch * 16);
            LDSM_X4(al[mt][0], al[mt][1], al[mt][2], al[mt][3],
                    uS + 6144 + arow * 48 + a_ch * 16);
        }
#pragma unroll
        for (int np = 0; np < 4; ++np) {
            int bn = wn * 64 + np * 16 + b_n0;
            uint32_t bh[4], bl[4];
            LDSM_X4(bh[0], bh[1], bh[2], bh[3],
                    uS + 12288 + bn * 48 + b_ch * 16);
            LDSM_X4(bl[0], bl[1], bl[2], bl[3],
                    uS + 18432 + bn * 48 + b_ch * 16);
#pragma unroll
            for (int mt = 0; mt < 2; ++mt) {
#pragma unroll
                for (int t = 0; t < 2; ++t) {
                    float* a4 = acc[mt][np * 2 + t];
                    MMA_BF16(a4, ah[mt], bh[2 * t], bh[2 * t + 1]);
                    MMA_BF16(a4, ah[mt], bl[2 * t], bl[2 * t + 1]);
                    MMA_BF16(a4, al[mt], bh[2 * t], bh[2 * t + 1]);
                }
            }
        }
        __syncthreads();
    }
}

// ---------------------------------------------------------------------------
// GEMM writing relu + bf16-split planes (G1, G3).
template <int K_DIM, int A_MODE>
__global__ __launch_bounds__(256, 2)
void mma_split(const float* __restrict__ Af,
               const __nv_bfloat16* __restrict__ Ah,
               const __nv_bfloat16* __restrict__ Al,
               const __nv_bfloat16* __restrict__ Bh,
               const __nv_bfloat16* __restrict__ Bl,
               const float* __restrict__ bias,
               __nv_bfloat16* __restrict__ Ch,
               __nv_bfloat16* __restrict__ Cl, int M) {
    __shared__ __align__(16) __nv_bfloat16 S[4 * 3072];
    const uint32_t uS = smem_u32(S);
    const int bm = blockIdx.x * 128;

    float acc[2][8][4];
#pragma unroll
    for (int i = 0; i < 2; ++i)
#pragma unroll
        for (int j = 0; j < 8; ++j)
#pragma unroll
            for (int q = 0; q < 4; ++q) acc[i][j][q] = 0.f;

    mma_mainloop<K_DIM, A_MODE>(Af, Ah, Al, Bh, Bl, M, bm, S, uS, acc);

    const int wid = threadIdx.x >> 5, lane = threadIdx.x & 31;
    const int wm = wid >> 1, wn = wid & 1;
    const int lr = lane >> 2, lc = (lane & 3) * 2;
#pragma unroll
    for (int mt = 0; mt < 2; ++mt) {
#pragma unroll
        for (int g = 0; g < 8; ++g) {
            int col = wn * 64 + g * 8 + lc;
            float2 bv = *(const float2*)&bias[col];
#pragma unroll
            for (int half = 0; half < 2; ++half) {
                int r = bm + wm * 32 + mt * 16 + lr + half * 8;
                if (r >= M) continue;
                float z0 = fmaxf(acc[mt][g][2 * half + 0] + bv.x, 0.f);
                float z1 = fmaxf(acc[mt][g][2 * half + 1] + bv.y, 0.f);
                __nv_bfloat16 h0, l0, h1, l1;
                bsplit(z0, h0, l0);
                bsplit(z1, h1, l1);
                size_t o = (size_t)r * HID + col;
                *(uint32_t*)(Ch + o) = pack_bf2(h0, h1);
                *(uint32_t*)(Cl + o) = pack_bf2(l0, l1);
            }
        }
    }
}

// Fused N=256 GEMM (grid.y = 2): y=0 -> out0 = val + bias0 (fp32);
// y=1 -> z5 = val + (Y1ACC ? z5 : b5p).
template <int K_DIM, int Y1ACC>
__global__ __launch_bounds__(256, 2)
void mma_fused(const __nv_bfloat16* __restrict__ Ah,
               const __nv_bfloat16* __restrict__ Al,
               const __nv_bfloat16* __restrict__ Bh,
               const __nv_bfloat16* __restrict__ Bl,
               const float* __restrict__ bias0,
               float* __restrict__ out0,
               const float* __restrict__ b5p,
               float* __restrict__ z5, int M) {
    __shared__ __align__(16) __nv_bfloat16 S[4 * 3072];
    const uint32_t uS = smem_u32(S);
    const int bm = blockIdx.x * 128;
    const int y  = blockIdx.y;
    const __nv_bfloat16* Bhy = Bh + (size_t)y * 128 * K_DIM;
    const __nv_bfloat16* Bly = Bl + (size_t)y * 128 * K_DIM;

    float acc[2][8][4];
#pragma unroll
    for (int i = 0; i < 2; ++i)
#pragma unroll
        for (int j = 0; j < 8; ++j)
#pragma unroll
            for (int q = 0; q < 4; ++q) acc[i][j][q] = 0.f;

    mma_mainloop<K_DIM, 1>(nullptr, Ah, Al, Bhy, Bly, M, bm, S, uS, acc);

    const int wid = threadIdx.x >> 5, lane = threadIdx.x & 31;
    const int wm = wid >> 1, wn = wid & 1;
    const int lr = lane >> 2, lc = (lane & 3) * 2;
#pragma unroll
    for (int mt = 0; mt < 2; ++mt) {
#pragma unroll
        for (int g = 0; g < 8; ++g) {
            int col = wn * 64 + g * 8 + lc;
#pragma unroll
            for (int half = 0; half < 2; ++half) {
                int r = bm + wm * 32 + mt * 16 + lr + half * 8;
                if (r >= M) continue;
                float z0 = acc[mt][g][2 * half + 0];
                float z1 = acc[mt][g][2 * half + 1];
                size_t o = (size_t)r * HID + col;
                if (y == 0) {
                    float2 bv = *(const float2*)&bias0[col];
                    *(float2*)&out0[o] = make_float2(z0 + bv.x, z1 + bv.y);
                } else {
                    float2 pv;
                    if (Y1ACC) pv = *(const float2*)&z5[o];
                    else       pv = *(const float2*)&b5p[col];
                    *(float2*)&z5[o] = make_float2(z0 + pv.x, z1 + pv.y);
                }
            }
        }
    }
}

// ---------------------------------------------------------------------------
// Classifier GEMM with fused LINKX combine in staging:
// h = relu(relu(z5) + hx + ha);  out = h @ wc + bc
__global__ __launch_bounds__(128)
void gemm_out(const float* __restrict__ z5,
              const float* __restrict__ hx,
              const float* __restrict__ ha,
              const float* __restrict__ W,
              const float* __restrict__ bias,
              float* __restrict__ out, int M) {
    __shared__ float As[16][128];
    __shared__ float Ws[16 * 40];

    const int tid = threadIdx.x;
    const int bm  = blockIdx.x * 128;
    const int ty  = tid >> 3;
    const int tx  = tid & 7;
    const int rm  = ty * 8;
    const int cn  = tx * 5;

    float acc[8][5];
#pragma unroll
    for (int i = 0; i < 8; ++i)
#pragma unroll
        for (int j = 0; j < 5; ++j) acc[i][j] = 0.f;

    for (int k0 = 0; k0 < 128; k0 += 16) {
#pragma unroll
        for (int u0 = 0; u0 < 512; u0 += 128) {
            int u   = u0 + tid;
            int row = u >> 2;
            int kq  = (u & 3) * 4;
            int grr = bm + row;
            float4 v = make_float4(0.f, 0.f, 0.f, 0.f);
            if (grr < M) {
                size_t o = (size_t)grr * 128 + k0 + kq;
                float4 z = *(const float4*)&z5[o];
                float4 a = *(const float4*)&hx[o];
                float4 b = *(const float4*)&ha[o];
                v.x = fmaxf(fmaxf(z.x, 0.f) + a.x + b.x, 0.f);
                v.y = fmaxf(fmaxf(z.y, 0.f) + a.y + b.y, 0.f);
                v.z = fmaxf(fmaxf(z.z, 0.f) + a.z + b.z, 0.f);
                v.w = fmaxf(fmaxf(z.w, 0.f) + a.w + b.w, 0.f);
            }
            As[kq + 0][row] = v.x;
            As[kq + 1][row] = v.y;
            As[kq + 2][row] = v.z;
            As[kq + 3][row] = v.w;
        }
        for (int u = tid; u < 16 * 40; u += 128) {
            int kr = u / 40, cc = u % 40;
            Ws[u] = W[(size_t)(k0 + kr) * 40 + cc];
        }
        __syncthreads();

#pragma unroll
        for (int kk = 0; kk < 16; ++kk) {
            float4 a0 = *(const float4*)&As[kk][rm];
            float4 a1 = *(const float4*)&As[kk][rm + 4];
            float a[8] = {a0.x, a0.y, a0.z, a0.w, a1.x, a1.y, a1.z, a1.w};
            float w[5];
#pragma unroll
            for (int j = 0; j < 5; ++j) w[j] = Ws[kk * 40 + cn + j];
#pragma unroll
            for (int i = 0; i < 8; ++i)
#pragma unroll
                for (int j = 0; j < 5; ++j)
                    acc[i][j] = fmaf(a[i], w[j], acc[i][j]);
        }
        __syncthreads();
    }

    float bb[5];
#pragma unroll
    for (int j = 0; j < 5; ++j) bb[j] = bias[cn + j];
#pragma unroll
    for (int i = 0; i < 8; ++i) {
        int r = bm + rm + i;
        if (r >= M) break;
#pragma unroll
        for (int j = 0; j < 5; ++j)
            out[(size_t)r * 40 + cn + j] = acc[i][j] + bb[j];
    }
}

// ---------------------------------------------------------------------------
extern "C" void kernel_launch(void* const* d_in, const int* in_sizes, int n_in,
                              void* d_out, int out_size) {
    const float* x   = (const float*)d_in[0];
    const int*   ei  = (const int*)  d_in[1];
    const float* emb = (const float*)d_in[2];
    const float* wx1 = (const float*)d_in[3];
    const float* bx1 = (const float*)d_in[4];
    const float* wx2 = (const float*)d_in[5];
    const float* bx2 = (const float*)d_in[6];
    const float* wa1 = (const float*)d_in[7];
    const float* ba1 = (const float*)d_in[8];
    const float* wa2 = (const float*)d_in[9];
    const float* ba2 = (const float*)d_in[10];
    const float* ww1 = (const float*)d_in[11];
    const float* bw1 = (const float*)d_in[12];
    const float* wc  = (const float*)d_in[13];
    const float* bc  = (const float*)d_in[14];
    float* out = (float*)d_out;

    const int M = in_sizes[0] / INDIM;   // 100000
    const int E = in_sizes[1] / 2;       // 1600000

    float *hx, *ha, *z5, *uv, *b5;
    __nv_bfloat16 *wt, *hb, *h2b, *aggb;
    int *cnt, *cur, *off, *bins;
    cudaGetSymbolAddress((void**)&hx,   g_hx);
    cudaGetSymbolAddress((void**)&ha,   g_ha);
    cudaGetSymbolAddress((void**)&z5,   g_z5);
    cudaGetSymbolAddress((void**)&uv,   g_uv);
    cudaGetSymbolAddress((void**)&b5,   g_b5);
    cudaGetSymbolAddress((void**)&wt,   g_wt);
    cudaGetSymbolAddress((void**)&hb,   g_hb);
    cudaGetSymbolAddress((void**)&h2b,  g_h2b);
    cudaGetSymbolAddress((void**)&aggb, g_aggb);
    cudaGetSymbolAddress((void**)&cnt,  g_cnt);
    cudaGetSymbolAddress((void**)&cur,  g_cur);
    cudaGetSymbolAddress((void**)&off,  g_off);
    cudaGetSymbolAddress((void**)&bins, g_bins);

    __nv_bfloat16 *hbh = hb,   *hbl = hb   + (size_t)M * HID;
    __nv_bfloat16 *h2h = h2b,  *h2l = h2b  + (size_t)M * HID;
    __nv_bfloat16 *agh = aggb, *agl = aggb + (size_t)M * HID;
    __nv_bfloat16 *W1h = wt,            *W1l = wt + 32768;
    __nv_bfloat16 *WB2h = wt + 65536,   *WB2l = wt + 98304;
    __nv_bfloat16 *W3h = wt + 131072,   *W3l = wt + 147456;
    __nv_bfloat16 *WB4h = wt + 163840,  *WB4l = wt + 196608;

    static cudaStream_t s_side = nullptr;
    static cudaEvent_t  ev_fork = nullptr, ev_prep = nullptr, ev_join = nullptr;
    if (s_side == nullptr) {
        cudaStreamCreateWithFlags(&s_side, cudaStreamNonBlocking);
        cudaEventCreateWithFlags(&ev_fork, cudaEventDisableTiming);
        cudaEventCreateWithFlags(&ev_prep, cudaEventDisableTiming);
        cudaEventCreateWithFlags(&ev_join, cudaEventDisableTiming);
    }

    const int gb = (M + 127) / 128;   // 782

    // ---- fork ----
    cudaEventRecord(ev_fork, 0);
    cudaStreamWaitEvent(s_side, ev_fork, 0);

    // side: binning + gather -> aggb planes
    zero_cnt<<<(M + 255) / 256, 256, 0, s_side>>>(cnt, cur, M);
    count_kernel<<<1184, 256, 0, s_side>>>(ei, cnt, E);
    scan_kernel<<<1, 1024, 0, s_side>>>(cnt, off, M);
    fill_kernel<<<1184, 256, 0, s_side>>>(ei, off, cur, bins, E);
    gather_kernel<<<(M * 32 + 255) / 256, 256, 0, s_side>>>(off, bins, emb, agh, agl, M);

    // main: composite weights + prep
    compose_kernel<<<dim3(128, 2), 128>>>(wx2, wa2, ww1, uv);
    bias5_kernel<<<1, 128>>>(bx2, ba2, bw1, ww1, b5);
    prep_all2<<<(114688 + 255) / 256, 256>>>(wx1, wx2, wa1, wa2, uv, wt);
    cudaEventRecord(ev_prep, 0);

    // side continues: G3: h2b = relu(aggb @ wa1 + ba1)  (needs ev_prep)
    cudaStreamWaitEvent(s_side, ev_prep, 0);
    mma_split<HID, 1><<<gb, 256, 0, s_side>>>(nullptr, agh, agl, W3h, W3l,
                                              ba1, h2h, h2l, M);
    cudaEventRecord(ev_join, s_side);

    // main: G1: hb = relu(x @ wx1 + bx1)  (splits x in staging)
    mma_split<INDIM, 0><<<gb, 256>>>(x, nullptr, nullptr, W1h, W1l,
                                     bx1, hbh, hbl, M);
    // main: fused G2|G5a: y0 -> hx = hb@wx2 + bx2; y1 -> z5 = hb@U + b5'
    mma_fused<HID, 0><<<dim3(gb, 2), 256>>>(hbh, hbl, WB2h, WB2l,
                                            bx2, hx, b5, z5, M);

    // ---- join ----
    cudaStreamWaitEvent(0, ev_join, 0);

    // fused G4|G5b: y0 -> ha = h2b@wa2 + ba2; y1 -> z5 += h2b@V
    mma_fused<HID, 1><<<dim3(gb, 2), 256>>>(h2h, h2l, WB4h, WB4l,
                                            ba2, ha, nullptr, z5, M);
    // G6: combine + classifier
    gemm_out<<<gb, 128>>>(z5, hx, ha, wc, bc, out, M);
}

// round 11
// speedup vs baseline: 1.0574x; 1.0574x over previous
#include <cuda_runtime.h>
#include <cuda_bf16.h>
#include <math.h>
#include <stdint.h>

// ---------------------------------------------------------------------------
// LINKX forward (R10 = R8 + G3/G4 on side stream + tensor-MMA classifier).
//  - Aggregation: counting-sort binning + warp-per-node gather; gather emits
//    bf16-split agg planes.
//  - GEMMs: mma.sync bf16 2-term split (hh+hl+lh), pre-split operands,
//    cp.async double-buffered staging (R8 mainloop, proven 503us).
//  - DAG: main: preps -> G1 -> G2 -> [join] -> G5 -> G6(MMA)
//         side: binning -> gather -> G3 -> G4
// ---------------------------------------------------------------------------

#define NMAX   100000
#define EMAX   1600000
#define HID    128
#define INDIM  256

// fp32 scratch
__device__ float g_hid[(size_t)NMAX * HID];        // G5 out -> G6 in
__device__ float g_cat[(size_t)NMAX * 2 * HID];    // fp32 residual (hx|ha)
// bf16-split activation planes (hi plane, then lo plane)
__device__ __align__(16) __nv_bfloat16 g_xs[2 * (size_t)NMAX * INDIM];
__device__ __align__(16) __nv_bfloat16 g_hb[2 * (size_t)NMAX * HID];
__device__ __align__(16) __nv_bfloat16 g_h2b[2 * (size_t)NMAX * HID];
__device__ __align__(16) __nv_bfloat16 g_aggb[2 * (size_t)NMAX * HID];
__device__ __align__(16) __nv_bfloat16 g_catb[2 * (size_t)NMAX * 2 * HID];
__device__ __align__(16) __nv_bfloat16 g_wt[245760];   // +16384 for padded wc
// binning scratch
__device__ int g_cnt[NMAX];
__device__ int g_cur[NMAX];
__device__ int g_off[NMAX + 1];
__device__ int g_bins[EMAX];

// ---- helpers --------------------------------------------------------------
__device__ __forceinline__ uint32_t smem_u32(const void* p) {
    uint32_t a;
    asm("{ .reg .u64 t; cvta.to.shared.u64 t, %1; cvt.u32.u64 %0, t; }"
        : "=r"(a) : "l"(p));
    return a;
}

#define LDSM_X4(r0, r1, r2, r3, addr) \
    asm volatile("ldmatrix.sync.aligned.m8n8.x4.shared.b16 {%0,%1,%2,%3}, [%4];" \
                 : "=r"(r0), "=r"(r1), "=r"(r2), "=r"(r3) : "r"(addr))

#define MMA_BF16(acc, a, b0v, b1v) \
    asm volatile("mma.sync.aligned.m16n8k16.row.col.f32.bf16.bf16.f32 " \
                 "{%0,%1,%2,%3}, {%4,%5,%6,%7}, {%8,%9}, {%0,%1,%2,%3};" \
                 : "+f"((acc)[0]), "+f"((acc)[1]), "+f"((acc)[2]), "+f"((acc)[3]) \
                 : "r"((a)[0]), "r"((a)[1]), "r"((a)[2]), "r"((a)[3]), \
                   "r"(b0v), "r"(b1v))

#define CP_ASYNC16(smem, gmem) \
    asm volatile("cp.async.cg.shared.global [%0], [%1], 16;" \
                 :: "r"(smem), "l"(gmem))
#define CP_COMMIT() asm volatile("cp.async.commit_group;")
#define CP_WAIT1()  asm volatile("cp.async.wait_group 1;")
#define CP_WAIT0()  asm volatile("cp.async.wait_group 0;")

__device__ __forceinline__ uint32_t pack_bf2(__nv_bfloat16 lo, __nv_bfloat16 hi) {
    __nv_bfloat162 p;
    p.x = lo; p.y = hi;
    return *reinterpret_cast<uint32_t*>(&p);
}

__device__ __forceinline__ void bsplit(float x, __nv_bfloat16& h, __nv_bfloat16& l) {
    h = __float2bfloat16(x);
    l = __float2bfloat16(x - __bfloat162float(h));
}

// ---------------------------------------------------------------------------
// Binning aggregation
// ---------------------------------------------------------------------------
__global__ void zero_cnt(int* cnt, int* cur, int M) {
    int i = blockIdx.x * blockDim.x + threadIdx.x;
    if (i < M) { cnt[i] = 0; cur[i] = 0; }
}

__global__ void count_kernel(const int* __restrict__ ei, int* __restrict__ cnt, int E) {
    int i = blockIdx.x * blockDim.x + threadIdx.x;
    int stride = gridDim.x * blockDim.x;
    for (int e = i; e < E; e += stride)
        atomicAdd(&cnt[__ldg(&ei[E + e])], 1);
}

__global__ void scan_kernel(const int* __restrict__ cnt, int* __restrict__ off, int M) {
    __shared__ int part[1024];
    const int t = threadIdx.x;
    const int chunk = (M + 1023) >> 10;
    const int beg = t * chunk;
    const int end = min(beg + chunk, M);
    int s = 0;
    for (int i = beg; i < end; ++i) s += cnt[i];
    part[t] = s;
    __syncthreads();
    for (int d = 1; d < 1024; d <<= 1) {
        int v = (t >= d) ? part[t - d] : 0;
        __syncthreads();
        part[t] += v;
        __syncthreads();
    }
    int run = (t == 0) ? 0 : part[t - 1];
    for (int i = beg; i < end; ++i) { off[i] = run; run += cnt[i]; }
    if (t == 1023) off[M] = run;
}

__global__ void fill_kernel(const int* __restrict__ ei,
                            const int* __restrict__ off,
                            int* __restrict__ cur,
                            int* __restrict__ bins, int E) {
    int i = blockIdx.x * blockDim.x + threadIdx.x;
    int stride = gridDim.x * blockDim.x;
    for (int e = i; e < E; e += stride) {
        int src = __ldg(&ei[e]);
        int dst = __ldg(&ei[E + e]);
        int slot = atomicAdd(&cur[dst], 1);
        bins[off[dst] + slot] = src;
    }
}

__global__ void gather_kernel(const int* __restrict__ off,
                              const int* __restrict__ bins,
                              const float* __restrict__ emb,
                              __nv_bfloat16* __restrict__ aggh,
                              __nv_bfloat16* __restrict__ aggl, int M) {
    int w    = (blockIdx.x * blockDim.x + threadIdx.x) >> 5;
    int lane = threadIdx.x & 31;
    if (w >= M) return;
    int beg = __ldg(&off[w]);
    int end = __ldg(&off[w + 1]);
    float4 acc = make_float4(0.f, 0.f, 0.f, 0.f);
    int e = beg;
    for (; e + 1 < end; e += 2) {
        int s0 = __ldg(&bins[e]);
        int s1 = __ldg(&bins[e + 1]);
        float4 v0 = __ldg((const float4*)(emb + (size_t)s0 * HID + lane * 4));
        float4 v1 = __ldg((const float4*)(emb + (size_t)s1 * HID + lane * 4));
        acc.x += v0.x + v1.x; acc.y += v0.y + v1.y;
        acc.z += v0.z + v1.z; acc.w += v0.w + v1.w;
    }
    if (e < end) {
        int s0 = __ldg(&bins[e]);
        float4 v0 = __ldg((const float4*)(emb + (size_t)s0 * HID + lane * 4));
        acc.x += v0.x; acc.y += v0.y; acc.z += v0.z; acc.w += v0.w;
    }
    float inv = 1.0f / (float)max(end - beg, 1);
    __nv_bfloat16 h0,h1,h2,h3, l0,l1,l2,l3;
    bsplit(acc.x * inv, h0, l0);
    bsplit(acc.y * inv, h1, l1);
    bsplit(acc.z * inv, h2, l2);
    bsplit(acc.w * inv, h3, l3);
    size_t o = (size_t)w * HID + lane * 4;
    *(uint2*)(aggh + o) = make_uint2(pack_bf2(h0, h1), pack_bf2(h2, h3));
    *(uint2*)(aggl + o) = make_uint2(pack_bf2(l0, l1), pack_bf2(l2, l3));
}

// ---------------------------------------------------------------------------
// x -> bf16 split planes
__global__ void prep_x(const float4* __restrict__ x4,
                       __nv_bfloat16* __restrict__ xh,
                       __nv_bfloat16* __restrict__ xl, int n4) {
    int t = blockIdx.x * blockDim.x + threadIdx.x;
    if (t >= n4) return;
    float4 v = __ldg(&x4[t]);
    __nv_bfloat16 h0,h1,h2,h3, l0,l1,l2,l3;
    bsplit(v.x, h0, l0); bsplit(v.y, h1, l1);
    bsplit(v.z, h2, l2); bsplit(v.w, h3, l3);
    ((uint2*)xh)[t] = make_uint2(pack_bf2(h0, h1), pack_bf2(h2, h3));
    ((uint2*)xl)[t] = make_uint2(pack_bf2(l0, l1), pack_bf2(l2, l3));
}

// Merged weight prep (5 matrices). Each segment: hi[128][K] | lo[128][K].
__global__ void prep_all(const float* __restrict__ wx1, const float* __restrict__ wx2,
                         const float* __restrict__ wa1, const float* __restrict__ wa2,
                         const float* __restrict__ ww1, __nv_bfloat16* __restrict__ WT) {
    int t = blockIdx.x * blockDim.x + threadIdx.x;
    const float* W;
    __nv_bfloat16* D;
    int K, base;
    if (t < 32768)      { W = wx1; D = WT;          K = 256; base = 0; }
    else if (t < 49152) { W = wx2; D = WT + 65536;  K = 128; base = 32768; }
    else if (t < 65536) { W = wa1; D = WT + 98304;  K = 128; base = 49152; }
    else if (t < 81920) { W = wa2; D = WT + 131072; K = 128; base = 65536; }
    else if (t < 114688){ W = ww1; D = WT + 163840; K = 256; base = 81920; }
    else return;
    int u = t - base;
    int k = u >> 7, n = u & 127;
    __nv_bfloat16 h, l;
    bsplit(W[u], h, l);
    D[(size_t)n * K + k] = h;
    D[(size_t)128 * K + (size_t)n * K + k] = l;
}

// wc [128,40] -> padded B^T [64][128] planes at g_wt + 229376 (hi | lo 8192 each)
__global__ void prep_wc(const float* __restrict__ wc, __nv_bfloat16* __restrict__ WT) {
    int t = blockIdx.x * blockDim.x + threadIdx.x;   // 8192
    if (t >= 8192) return;
    int n = t >> 7, k = t & 127;                     // n 0..63, k 0..127
    float v = (n < 40) ? wc[k * 40 + n] : 0.f;
    __nv_bfloat16 h, l;
    bsplit(v, h, l);
    WT[229376 + (size_t)n * 128 + k] = h;
    WT[237568 + (size_t)n * 128 + k] = l;
}

// ---------------------------------------------------------------------------
// cp.async double-buffered bf16-split MMA GEMM (R8, proven).
template <int K_DIM, int RELU, int WBF, int WF32, int COMBINE>
__global__ __launch_bounds__(256, 2)
void mma_gemm2(const __nv_bfloat16* __restrict__ Ah,
               const __nv_bfloat16* __restrict__ Al,
               const __nv_bfloat16* __restrict__ Bh,
               const __nv_bfloat16* __restrict__ Bl,
               const float* __restrict__ bias,
               __nv_bfloat16* __restrict__ Cbh,
               __nv_bfloat16* __restrict__ Cbl, int ldcb,
               float* __restrict__ Cf,
               const float* __restrict__ res,
               int ldc, int coff, int M) {
    __shared__ __align__(16) __nv_bfloat16 S[2][4][128 * 24];

    const int tid  = threadIdx.x;
    const int wid  = tid >> 5;
    const int lane = tid & 31;
    const int wm   = wid >> 1;
    const int wn   = wid & 1;
    const int bm   = blockIdx.x * 128;

    const uint32_t uS = smem_u32(S);
    const int srow = tid >> 1;
    const int sh   = tid & 1;
    const int gr   = min(bm + srow, M - 1);

    const __nv_bfloat16* pAh = Ah + (size_t)gr * K_DIM + sh * 8;
    const __nv_bfloat16* pAl = Al + (size_t)gr * K_DIM + sh * 8;
    const __nv_bfloat16* pBh = Bh + (size_t)srow * K_DIM + sh * 8;
    const __nv_bfloat16* pBl = Bl + (size_t)srow * K_DIM + sh * 8;
    const uint32_t sdst = uS + srow * 48 + sh * 16;

#define ISSUE_STAGE(c, s) do {                                   \
        int _k0 = (c) * 16;                                      \
        uint32_t _b = sdst + (s) * 24576;                        \
        CP_ASYNC16(_b,          pAh + _k0);                      \
        CP_ASYNC16(_b + 6144,   pAl + _k0);                      \
        CP_ASYNC16(_b + 12288,  pBh + _k0);                      \
        CP_ASYNC16(_b + 18432,  pBl + _k0);                      \
        CP_COMMIT();                                             \
    } while (0)

    float acc[2][8][4];
#pragma unroll
    for (int i = 0; i < 2; ++i)
#pragma unroll
        for (int j = 0; j < 8; ++j)
#pragma unroll
            for (int q = 0; q < 4; ++q) acc[i][j][q] = 0.f;

    const int a_r0 = (lane & 7) + ((lane >> 3) & 1) * 8;
    const int a_ch = lane >> 4;
    const int b_n0 = (lane & 7) + ((lane >> 4) & 1) * 8;
    const int b_ch = (lane >> 3) & 1;

    const int NC = K_DIM / 16;
    ISSUE_STAGE(0, 0);

    for (int c = 0; c < NC; ++c) {
        const int s = c & 1;
        if (c + 1 < NC) { ISSUE_STAGE(c + 1, (c + 1) & 1); CP_WAIT1(); }
        else            { CP_WAIT0(); }
        __syncthreads();

        const uint32_t base = uS + s * 24576;
        uint32_t ah[2][4], al[2][4];
#pragma unroll
        for (int mt = 0; mt < 2; ++mt) {
            int arow = wm * 32 + mt * 16 + a_r0;
            LDSM_X4(ah[mt][0], ah[mt][1], ah[mt][2], ah[mt][3],
                    base + arow * 48 + a_ch * 16);
            LDSM_X4(al[mt][0], al[mt][1], al[mt][2], al[mt][3],
                    base + 6144 + arow * 48 + a_ch * 16);
        }
#pragma unroll
        for (int np = 0; np < 4; ++np) {
            int bn = wn * 64 + np * 16 + b_n0;
            uint32_t bh[4], bl[4];
            LDSM_X4(bh[0], bh[1], bh[2], bh[3],
                    base + 12288 + bn * 48 + b_ch * 16);
            LDSM_X4(bl[0], bl[1], bl[2], bl[3],
                    base + 18432 + bn * 48 + b_ch * 16);
#pragma unroll
            for (int mt = 0; mt < 2; ++mt) {
#pragma unroll
                for (int t = 0; t < 2; ++t) {
                    float* a4 = acc[mt][np * 2 + t];
                    MMA_BF16(a4, ah[mt], bh[2 * t], bh[2 * t + 1]);
                    MMA_BF16(a4, ah[mt], bl[2 * t], bl[2 * t + 1]);
                    MMA_BF16(a4, al[mt], bh[2 * t], bh[2 * t + 1]);
                }
            }
        }
        __syncthreads();
    }
#undef ISSUE_STAGE

    const int lr = lane >> 2;
    const int lc = (lane & 3) * 2;
#pragma unroll
    for (int mt = 0; mt < 2; ++mt) {
#pragma unroll
        for (int g = 0; g < 8; ++g) {
            int col = wn * 64 + g * 8 + lc;
            float2 bv = *(const float2*)&bias[col];
#pragma unroll
            for (int half = 0; half < 2; ++half) {
                int r = bm + wm * 32 + mt * 16 + lr + half * 8;
                if (r >= M) continue;
                float z0 = acc[mt][g][2 * half + 0] + bv.x;
                float z1 = acc[mt][g][2 * half + 1] + bv.y;
                if (RELU) { z0 = fmaxf(z0, 0.f); z1 = fmaxf(z1, 0.f); }
                if (COMBINE) {
                    const float* rrow = res + (size_t)r * 256;
                    float2 hx = *(const float2*)&rrow[col];
                    float2 ha = *(const float2*)&rrow[128 + col];
                    z0 = fmaxf(fmaxf(z0, 0.f) + hx.x + ha.x, 0.f);
                    z1 = fmaxf(fmaxf(z1, 0.f) + hx.y + ha.y, 0.f);
                }
                if (WF32)
                    *(float2*)&Cf[(size_t)r * ldc + coff + col] = make_float2(z0, z1);
                if (WBF) {
                    __nv_bfloat16 h0, l0, h1, l1;
                    bsplit(z0, h0, l0);
                    bsplit(z1, h1, l1);
                    size_t o = (size_t)r * ldcb + coff + col;
                    *(uint32_t*)(Cbh + o) = pack_bf2(h0, h1);
                    *(uint32_t*)(Cbl + o) = pack_bf2(l0, l1);
                }
            }
        }
    }
}

// ---------------------------------------------------------------------------
// Tensor-MMA classifier: out[M,40] = hid @ wc + bc  (wc padded to 64 cols).
// M-tile 128, N 64, K 128. 8 warps, each owns 16 rows x 64 cols.
// A (hid fp32) split in staging; B from pre-split padded planes.
__global__ __launch_bounds__(256, 2)
void mma_out(const float* __restrict__ A,
             const __nv_bfloat16* __restrict__ Bh,
             const __nv_bfloat16* __restrict__ Bl,
             const float* __restrict__ bias,
             float* __restrict__ out, int M) {
    __shared__ __align__(16) __nv_bfloat16 AH[128 * 24];
    __shared__ __align__(16) __nv_bfloat16 AL[128 * 24];
    __shared__ __align__(16) __nv_bfloat16 BHs[64 * 24];
    __shared__ __align__(16) __nv_bfloat16 BLs[64 * 24];

    const int tid  = threadIdx.x;
    const int wid  = tid >> 5;
    const int lane = tid & 31;
    const int bm   = blockIdx.x * 128;

    const uint32_t uAH = smem_u32(AH);
    const uint32_t uAL = smem_u32(AL);
    const uint32_t uBH = smem_u32(BHs);
    const uint32_t uBL = smem_u32(BLs);

    float acc[8][4];
#pragma unroll
    for (int j = 0; j < 8; ++j)
#pragma unroll
        for (int q = 0; q < 4; ++q) acc[j][q] = 0.f;

    const int a_r0 = (lane & 7) + ((lane >> 3) & 1) * 8;
    const int a_ch = lane >> 4;
    const int b_n0 = (lane & 7) + ((lane >> 4) & 1) * 8;
    const int b_ch = (lane >> 3) & 1;
    const int srow = tid >> 1;
    const int sh   = tid & 1;

    for (int c = 0; c < 8; ++c) {
        const int k0 = c * 16;
        {   // A staging: fp32 -> bf16 split
            int gr = bm + srow;
            float4 v0 = make_float4(0.f, 0.f, 0.f, 0.f), v1 = v0;
            if (gr < M) {
                const float* p = A + (size_t)gr * 128 + k0 + sh * 8;
                v0 = *(const float4*)p;
                v1 = *(const float4*)(p + 4);
            }
            __nv_bfloat16 h0,h1,h2,h3,h4,h5,h6,h7, l0,l1,l2,l3,l4,l5,l6,l7;
            bsplit(v0.x, h0, l0); bsplit(v0.y, h1, l1);
            bsplit(v0.z, h2, l2); bsplit(v0.w, h3, l3);
            bsplit(v1.x, h4, l4); bsplit(v1.y, h5, l5);
            bsplit(v1.z, h6, l6); bsplit(v1.w, h7, l7);
            *(uint4*)&AH[srow * 24 + sh * 8] =
                make_uint4(pack_bf2(h0,h1), pack_bf2(h2,h3),
                           pack_bf2(h4,h5), pack_bf2(h6,h7));
            *(uint4*)&AL[srow * 24 + sh * 8] =
                make_uint4(pack_bf2(l0,l1), pack_bf2(l2,l3),
                           pack_bf2(l4,l5), pack_bf2(l6,l7));
        }
        if (tid < 128) {   // B staging (64 rows)
            *(uint4*)&BHs[srow * 24 + sh * 8] =
                *(const uint4*)&Bh[(size_t)srow * 128 + k0 + sh * 8];
            *(uint4*)&BLs[srow * 24 + sh * 8] =
                *(const uint4*)&Bl[(size_t)srow * 128 + k0 + sh * 8];
        }
        __syncthreads();

        uint32_t ah[4], al[4];
        int arow = wid * 16 + a_r0;
        LDSM_X4(ah[0], ah[1], ah[2], ah[3], uAH + arow * 48 + a_ch * 16);
        LDSM_X4(al[0], al[1], al[2], al[3], uAL + arow * 48 + a_ch * 16);
#pragma unroll
        for (int np = 0; np < 4; ++np) {
            int bn = np * 16 + b_n0;
            uint32_t bh[4], bl[4];
            LDSM_X4(bh[0], bh[1], bh[2], bh[3], uBH + bn * 48 + b_ch * 16);
            LDSM_X4(bl[0], bl[1], bl[2], bl[3], uBL + bn * 48 + b_ch * 16);
#pragma unroll
            for (int t = 0; t < 2; ++t) {
                float* a4 = acc[np * 2 + t];
                MMA_BF16(a4, ah, bh[2 * t], bh[2 * t + 1]);
                MMA_BF16(a4, ah, bl[2 * t], bl[2 * t + 1]);
                MMA_BF16(a4, al, bh[2 * t], bh[2 * t + 1]);
            }
        }
        __syncthreads();
    }

    const int lr = lane >> 2;
    const int lc = (lane & 3) * 2;
#pragma unroll
    for (int g = 0; g < 8; ++g) {
        int col = g * 8 + lc;
        if (col >= 40) continue;
        float2 bv = *(const float2*)&bias[col];
#pragma unroll
        for (int half = 0; half < 2; ++half) {
            int r = bm + wid * 16 + lr + half * 8;
            if (r >= M) continue;
            float z0 = acc[g][2 * half + 0] + bv.x;
            float z1 = acc[g][2 * half + 1] + bv.y;
            *(float2*)&out[(size_t)r * 40 + col] = make_float2(z0, z1);
        }
    }
}

// ---------------------------------------------------------------------------
extern "C" void kernel_launch(void* const* d_in, const int* in_sizes, int n_in,
                              void* d_out, int out_size) {
    const float* x   = (const float*)d_in[0];
    const int*   ei  = (const int*)  d_in[1];
    const float* emb = (const float*)d_in[2];
    const float* wx1 = (const float*)d_in[3];
    const float* bx1 = (const float*)d_in[4];
    const float* wx2 = (const float*)d_in[5];
    const float* bx2 = (const float*)d_in[6];
    const float* wa1 = (const float*)d_in[7];
    const float* ba1 = (const float*)d_in[8];
    const float* wa2 = (const float*)d_in[9];
    const float* ba2 = (const float*)d_in[10];
    const float* ww1 = (const float*)d_in[11];
    const float* bw1 = (const float*)d_in[12];
    const float* wc  = (const float*)d_in[13];
    const float* bc  = (const float*)d_in[14];
    float* out = (float*)d_out;

    const int M = in_sizes[0] / INDIM;   // 100000
    const int E = in_sizes[1] / 2;       // 1600000

    float *hid, *cat;
    __nv_bfloat16 *wt, *xs, *hb, *h2b, *aggb, *catb;
    int *cnt, *cur, *off, *bins;
    cudaGetSymbolAddress((void**)&hid,  g_hid);
    cudaGetSymbolAddress((void**)&cat,  g_cat);
    cudaGetSymbolAddress((void**)&wt,   g_wt);
    cudaGetSymbolAddress((void**)&xs,   g_xs);
    cudaGetSymbolAddress((void**)&hb,   g_hb);
    cudaGetSymbolAddress((void**)&h2b,  g_h2b);
    cudaGetSymbolAddress((void**)&aggb, g_aggb);
    cudaGetSymbolAddress((void**)&catb, g_catb);
    cudaGetSymbolAddress((void**)&cnt,  g_cnt);
    cudaGetSymbolAddress((void**)&cur,  g_cur);
    cudaGetSymbolAddress((void**)&off,  g_off);
    cudaGetSymbolAddress((void**)&bins, g_bins);

    __nv_bfloat16 *xsh = xs,   *xsl = xs   + (size_t)M * INDIM;
    __nv_bfloat16 *hbh = hb,   *hbl = hb   + (size_t)M * HID;
    __nv_bfloat16 *h2h = h2b,  *h2l = h2b  + (size_t)M * HID;
    __nv_bfloat16 *agh = aggb, *agl = aggb + (size_t)M * HID;
    __nv_bfloat16 *cbh = catb, *cbl = catb + (size_t)M * 2 * HID;
    __nv_bfloat16 *W1h = wt,           *W1l = wt + 32768;
    __nv_bfloat16 *W2h = wt + 65536,   *W2l = wt + 81920;
    __nv_bfloat16 *W3h = wt + 98304,   *W3l = wt + 114688;
    __nv_bfloat16 *W4h = wt + 131072,  *W4l = wt + 147456;
    __nv_bfloat16 *W5h = wt + 163840,  *W5l = wt + 196608;
    __nv_bfloat16 *W6h = wt + 229376,  *W6l = wt + 237568;

    static cudaStream_t s_side = nullptr;
    static cudaEvent_t  ev_fork = nullptr, ev_prep = nullptr, ev_join = nullptr;
    if (s_side == nullptr) {
        cudaStreamCreateWithFlags(&s_side, cudaStreamNonBlocking);
        cudaEventCreateWithFlags(&ev_fork, cudaEventDisableTiming);
        cudaEventCreateWithFlags(&ev_prep, cudaEventDisableTiming);
        cudaEventCreateWithFlags(&ev_join, cudaEventDisableTiming);
    }

    const int gb = (M + 127) / 128;   // 782

    // ---- fork ----
    cudaEventRecord(ev_fork, 0);
    cudaStreamWaitEvent(s_side, ev_fork, 0);

    // side: binning + gather -> aggb planes
    zero_cnt<<<(M + 255) / 256, 256, 0, s_side>>>(cnt, cur, M);
    count_kernel<<<1184, 256, 0, s_side>>>(ei, cnt, E);
    scan_kernel<<<1, 1024, 0, s_side>>>(cnt, off, M);
    fill_kernel<<<1184, 256, 0, s_side>>>(ei, off, cur, bins, E);
    gather_kernel<<<(M * 32 + 255) / 256, 256, 0, s_side>>>(off, bins, emb, agh, agl, M);

    // main: preps
    prep_all<<<(114688 + 255) / 256, 256>>>(wx1, wx2, wa1, wa2, ww1, wt);
    prep_wc<<<(8192 + 255) / 256, 256>>>(wc, wt);
    const int n4x = M * (INDIM / 4);
    prep_x<<<(n4x + 255) / 256, 256>>>((const float4*)x, xsh, xsl, n4x);
    cudaEventRecord(ev_prep, 0);

    // side continues after prep: G3 then G4
    cudaStreamWaitEvent(s_side, ev_prep, 0);
    // G3: h2b = relu(aggb @ wa1 + ba1)        [bf16-split out]
    mma_gemm2<HID, 1, 1, 0, 0><<<gb, 256, 0, s_side>>>(agh, agl, W3h, W3l, ba1,
                                                       h2h, h2l, HID, nullptr, nullptr, 0, 0, M);
    // G4: cat[:,128:256] = h2b @ wa2 + ba2    [bf16-split + fp32 out]
    mma_gemm2<HID, 0, 1, 1, 0><<<gb, 256, 0, s_side>>>(h2h, h2l, W4h, W4l, ba2,
                                                       cbh, cbl, 256, cat, nullptr, 256, 128, M);
    cudaEventRecord(ev_join, s_side);

    // main: G1: hb = relu(x @ wx1 + bx1)      [bf16-split out]
    mma_gemm2<INDIM, 1, 1, 0, 0><<<gb, 256>>>(xsh, xsl, W1h, W1l, bx1,
                                              hbh, hbl, HID, nullptr, nullptr, 0, 0, M);
    // main: G2: cat[:,0:128] = hb @ wx2 + bx2 [bf16-split + fp32 out]
    mma_gemm2<HID, 0, 1, 1, 0><<<gb, 256>>>(hbh, hbl, W2h, W2l, bx2,
                                            cbh, cbl, 256, cat, nullptr, 256, 0, M);

    // ---- join ----
    cudaStreamWaitEvent(0, ev_join, 0);

    // G5: hid = relu(relu(catb @ ww1 + bw1) + hx + ha)   [fp32 out]
    mma_gemm2<2 * HID, 0, 0, 1, 1><<<gb, 256>>>(cbh, cbl, W5h, W5l, bw1,
                                                nullptr, nullptr, 0, hid, cat, 128, 0, M);
    // G6: tensor-MMA classifier
    mma_out<<<gb, 256>>>(hid, W6h, W6l, bc, out, M);
}

// round 15
// speedup vs baseline: 1.1268x; 1.0656x over previous
#include <cuda_runtime.h>
#include <cuda_bf16.h>
#include <math.h>
#include <stdint.h>

// ---------------------------------------------------------------------------
// LINKX forward (R12 = R11 + k32 double-buffered MMA mainloop).
//  - Aggregation: counting-sort binning + warp-per-node gather (bf16-split out).
//  - GEMMs: mma.sync bf16 2-term split (hh+hl+lh), pre-split operands,
//    k-chunk 32, 2-stage cp.async, one barrier pair per 32-k (was per 16-k).
//  - DAG: main: preps -> G1 -> G2 -> [join] -> G5 -> G6(MMA)
//         side: binning -> gather -> G3 -> G4
// ---------------------------------------------------------------------------

#define NMAX   100000
#define EMAX   1600000
#define HID    128
#define INDIM  256

// fp32 scratch
__device__ float g_hid[(size_t)NMAX * HID];
__device__ float g_cat[(size_t)NMAX * 2 * HID];
// bf16-split activation planes (hi plane, then lo plane)
__device__ __align__(16) __nv_bfloat16 g_xs[2 * (size_t)NMAX * INDIM];
__device__ __align__(16) __nv_bfloat16 g_hb[2 * (size_t)NMAX * HID];
__device__ __align__(16) __nv_bfloat16 g_h2b[2 * (size_t)NMAX * HID];
__device__ __align__(16) __nv_bfloat16 g_aggb[2 * (size_t)NMAX * HID];
__device__ __align__(16) __nv_bfloat16 g_catb[2 * (size_t)NMAX * 2 * HID];
__device__ __align__(16) __nv_bfloat16 g_wt[245760];
// binning scratch
__device__ int g_cnt[NMAX];
__device__ int g_cur[NMAX];
__device__ int g_off[NMAX + 1];
__device__ int g_bins[EMAX];

// ---- helpers --------------------------------------------------------------
__device__ __forceinline__ uint32_t smem_u32(const void* p) {
    uint32_t a;
    asm("{ .reg .u64 t; cvta.to.shared.u64 t, %1; cvt.u32.u64 %0, t; }"
        : "=r"(a) : "l"(p));
    return a;
}

#define LDSM_X4(r0, r1, r2, r3, addr) \
    asm volatile("ldmatrix.sync.aligned.m8n8.x4.shared.b16 {%0,%1,%2,%3}, [%4];" \
                 : "=r"(r0), "=r"(r1), "=r"(r2), "=r"(r3) : "r"(addr))

#define MMA_BF16(acc, a, b0v, b1v) \
    asm volatile("mma.sync.aligned.m16n8k16.row.col.f32.bf16.bf16.f32 " \
                 "{%0,%1,%2,%3}, {%4,%5,%6,%7}, {%8,%9}, {%0,%1,%2,%3};" \
                 : "+f"((acc)[0]), "+f"((acc)[1]), "+f"((acc)[2]), "+f"((acc)[3]) \
                 : "r"((a)[0]), "r"((a)[1]), "r"((a)[2]), "r"((a)[3]), \
                   "r"(b0v), "r"(b1v))

#define CP_ASYNC16(smem, gmem) \
    asm volatile("cp.async.cg.shared.global [%0], [%1], 16;" \
                 :: "r"(smem), "l"(gmem))
#define CP_COMMIT() asm volatile("cp.async.commit_group;")
#define CP_WAIT1()  asm volatile("cp.async.wait_group 1;")
#define CP_WAIT0()  asm volatile("cp.async.wait_group 0;")

__device__ __forceinline__ uint32_t pack_bf2(__nv_bfloat16 lo, __nv_bfloat16 hi) {
    __nv_bfloat162 p;
    p.x = lo; p.y = hi;
    return *reinterpret_cast<uint32_t*>(&p);
}

__device__ __forceinline__ void bsplit(float x, __nv_bfloat16& h, __nv_bfloat16& l) {
    h = __float2bfloat16(x);
    l = __float2bfloat16(x - __bfloat162float(h));
}

// ---------------------------------------------------------------------------
// Binning aggregation (unchanged, proven)
// ---------------------------------------------------------------------------
__global__ void zero_cnt(int* cnt, int* cur, int M) {
    int i = blockIdx.x * blockDim.x + threadIdx.x;
    if (i < M) { cnt[i] = 0; cur[i] = 0; }
}

__global__ void count_kernel(const int* __restrict__ ei, int* __restrict__ cnt, int E) {
    int i = blockIdx.x * blockDim.x + threadIdx.x;
    int stride = gridDim.x * blockDim.x;
    for (int e = i; e < E; e += stride)
        atomicAdd(&cnt[__ldg(&ei[E + e])], 1);
}

__global__ void scan_kernel(const int* __restrict__ cnt, int* __restrict__ off, int M) {
    __shared__ int part[1024];
    const int t = threadIdx.x;
    const int chunk = (M + 1023) >> 10;
    const int beg = t * chunk;
    const int end = min(beg + chunk, M);
    int s = 0;
    for (int i = beg; i < end; ++i) s += cnt[i];
    part[t] = s;
    __syncthreads();
    for (int d = 1; d < 1024; d <<= 1) {
        int v = (t >= d) ? part[t - d] : 0;
        __syncthreads();
        part[t] += v;
        __syncthreads();
    }
    int run = (t == 0) ? 0 : part[t - 1];
    for (int i = beg; i < end; ++i) { off[i] = run; run += cnt[i]; }
    if (t == 1023) off[M] = run;
}

__global__ void fill_kernel(const int* __restrict__ ei,
                            const int* __restrict__ off,
                            int* __restrict__ cur,
                            int* __restrict__ bins, int E) {
    int i = blockIdx.x * blockDim.x + threadIdx.x;
    int stride = gridDim.x * blockDim.x;
    for (int e = i; e < E; e += stride) {
        int src = __ldg(&ei[e]);
        int dst = __ldg(&ei[E + e]);
        int slot = atomicAdd(&cur[dst], 1);
        bins[off[dst] + slot] = src;
    }
}

__global__ void gather_kernel(const int* __restrict__ off,
                              const int* __restrict__ bins,
                              const float* __restrict__ emb,
                              __nv_bfloat16* __restrict__ aggh,
                              __nv_bfloat16* __restrict__ aggl, int M) {
    int w    = (blockIdx.x * blockDim.x + threadIdx.x) >> 5;
    int lane = threadIdx.x & 31;
    if (w >= M) return;
    int beg = __ldg(&off[w]);
    int end = __ldg(&off[w + 1]);
    float4 acc = make_float4(0.f, 0.f, 0.f, 0.f);
    int e = beg;
    for (; e + 1 < end; e += 2) {
        int s0 = __ldg(&bins[e]);
        int s1 = __ldg(&bins[e + 1]);
        float4 v0 = __ldg((const float4*)(emb + (size_t)s0 * HID + lane * 4));
        float4 v1 = __ldg((const float4*)(emb + (size_t)s1 * HID + lane * 4));
        acc.x += v0.x + v1.x; acc.y += v0.y + v1.y;
        acc.z += v0.z + v1.z; acc.w += v0.w + v1.w;
    }
    if (e < end) {
        int s0 = __ldg(&bins[e]);
        float4 v0 = __ldg((const float4*)(emb + (size_t)s0 * HID + lane * 4));
        acc.x += v0.x; acc.y += v0.y; acc.z += v0.z; acc.w += v0.w;
    }
    float inv = 1.0f / (float)max(end - beg, 1);
    __nv_bfloat16 h0,h1,h2,h3, l0,l1,l2,l3;
    bsplit(acc.x * inv, h0, l0);
    bsplit(acc.y * inv, h1, l1);
    bsplit(acc.z * inv, h2, l2);
    bsplit(acc.w * inv, h3, l3);
    size_t o = (size_t)w * HID + lane * 4;
    *(uint2*)(aggh + o) = make_uint2(pack_bf2(h0, h1), pack_bf2(h2, h3));
    *(uint2*)(aggl + o) = make_uint2(pack_bf2(l0, l1), pack_bf2(l2, l3));
}

// ---------------------------------------------------------------------------
__global__ void prep_x(const float4* __restrict__ x4,
                       __nv_bfloat16* __restrict__ xh,
                       __nv_bfloat16* __restrict__ xl, int n4) {
    int t = blockIdx.x * blockDim.x + threadIdx.x;
    if (t >= n4) return;
    float4 v = __ldg(&x4[t]);
    __nv_bfloat16 h0,h1,h2,h3, l0,l1,l2,l3;
    bsplit(v.x, h0, l0); bsplit(v.y, h1, l1);
    bsplit(v.z, h2, l2); bsplit(v.w, h3, l3);
    ((uint2*)xh)[t] = make_uint2(pack_bf2(h0, h1), pack_bf2(h2, h3));
    ((uint2*)xl)[t] = make_uint2(pack_bf2(l0, l1), pack_bf2(l2, l3));
}

__global__ void prep_all(const float* __restrict__ wx1, const float* __restrict__ wx2,
                         const float* __restrict__ wa1, const float* __restrict__ wa2,
                         const float* __restrict__ ww1, __nv_bfloat16* __restrict__ WT) {
    int t = blockIdx.x * blockDim.x + threadIdx.x;
    const float* W;
    __nv_bfloat16* D;
    int K, base;
    if (t < 32768)      { W = wx1; D = WT;          K = 256; base = 0; }
    else if (t < 49152) { W = wx2; D = WT + 65536;  K = 128; base = 32768; }
    else if (t < 65536) { W = wa1; D = WT + 98304;  K = 128; base = 49152; }
    else if (t < 81920) { W = wa2; D = WT + 131072; K = 128; base = 65536; }
    else if (t < 114688){ W = ww1; D = WT + 163840; K = 256; base = 81920; }
    else return;
    int u = t - base;
    int k = u >> 7, n = u & 127;
    __nv_bfloat16 h, l;
    bsplit(W[u], h, l);
    D[(size_t)n * K + k] = h;
    D[(size_t)128 * K + (size_t)n * K + k] = l;
}

__global__ void prep_wc(const float* __restrict__ wc, __nv_bfloat16* __restrict__ WT) {
    int t = blockIdx.x * blockDim.x + threadIdx.x;
    if (t >= 8192) return;
    int n = t >> 7, k = t & 127;
    float v = (n < 40) ? wc[k * 40 + n] : 0.f;
    __nv_bfloat16 h, l;
    bsplit(v, h, l);
    WT[229376 + (size_t)n * 128 + k] = h;
    WT[237568 + (size_t)n * 128 + k] = l;
}

// ---------------------------------------------------------------------------
// k32 double-buffered bf16-split MMA GEMM.
// Dynamic smem: 2 stages x 4 planes x 128 rows x 40 elems (80B stride) = 80KB.
// Plane order per stage: AH(0) AL(10240) BH(20480) BL(30720) bytes.
// ---------------------------------------------------------------------------
template <int K_DIM, int RELU, int WBF, int WF32, int COMBINE>
__global__ __launch_bounds__(256, 2)
void mma_gemm3(const __nv_bfloat16* __restrict__ Ah,
               const __nv_bfloat16* __restrict__ Al,
               const __nv_bfloat16* __restrict__ Bh,
               const __nv_bfloat16* __restrict__ Bl,
               const float* __restrict__ bias,
               __nv_bfloat16* __restrict__ Cbh,
               __nv_bfloat16* __restrict__ Cbl, int ldcb,
               float* __restrict__ Cf,
               const float* __restrict__ res,
               int ldc, int coff, int M) {
    extern __shared__ __align__(16) __nv_bfloat16 S[];

    const int tid  = threadIdx.x;
    const int wid  = tid >> 5;
    const int lane = tid & 31;
    const int wm   = wid >> 1;
    const int wn   = wid & 1;
    const int bm   = blockIdx.x * 128;
    const uint32_t uS = smem_u32(S);

    // ---- staging plan: 2048 16B units per stage, 8 per thread ----
    const __nv_bfloat16* gp[8];
    uint32_t so[8];
#pragma unroll
    for (int i = 0; i < 8; ++i) {
        int u   = tid + i * 256;
        int p   = u >> 9;            // plane 0..3
        int rem = u & 511;
        int row = rem >> 2;          // 0..127
        int q   = rem & 3;           // 16B quarter of 64B row
        so[i] = (uint32_t)(p * 10240 + row * 80 + q * 16);
        if (p == 0)      gp[i] = Ah + (size_t)min(bm + row, M - 1) * K_DIM + q * 8;
        else if (p == 1) gp[i] = Al + (size_t)min(bm + row, M - 1) * K_DIM + q * 8;
        else if (p == 2) gp[i] = Bh + (size_t)row * K_DIM + q * 8;
        else             gp[i] = Bl + (size_t)row * K_DIM + q * 8;
    }

#define ISSUE_STAGE(c, s) do {                                    \
        uint32_t _b = uS + (s) * 40960;                           \
        int _k0 = (c) * 32;                                       \
        _Pragma("unroll")                                         \
        for (int _i = 0; _i < 8; ++_i)                            \
            CP_ASYNC16(_b + so[_i], gp[_i] + _k0);                \
        CP_COMMIT();                                              \
    } while (0)

    float acc[2][8][4];
#pragma unroll
    for (int i = 0; i < 2; ++i)
#pragma unroll
        for (int j = 0; j < 8; ++j)
#pragma unroll
            for (int q = 0; q < 4; ++q) acc[i][j][q] = 0.f;

    const int a_r0 = (lane & 7) + ((lane >> 3) & 1) * 8;
    const int a_ch = lane >> 4;
    const int b_n0 = (lane & 7) + ((lane >> 4) & 1) * 8;
    const int b_ch = (lane >> 3) & 1;

    const int NC = K_DIM / 32;
    ISSUE_STAGE(0, 0);

    for (int c = 0; c < NC; ++c) {
        const int s = c & 1;
        if (c + 1 < NC) { ISSUE_STAGE(c + 1, (c + 1) & 1); CP_WAIT1(); }
        else            { CP_WAIT0(); }
        __syncthreads();

        const uint32_t base = uS + s * 40960;
#pragma unroll
        for (int kk = 0; kk < 2; ++kk) {
            const uint32_t koff = kk * 32 + (uint32_t)(a_ch * 16);
            uint32_t ah[2][4], al[2][4];
#pragma unroll
            for (int mt = 0; mt < 2; ++mt) {
                int arow = wm * 32 + mt * 16 + a_r0;
                LDSM_X4(ah[mt][0], ah[mt][1], ah[mt][2], ah[mt][3],
                        base + arow * 80 + koff);
                LDSM_X4(al[mt][0], al[mt][1], al[mt][2], al[mt][3],
                        base + 10240 + arow * 80 + koff);
            }
            const uint32_t bkoff = kk * 32 + (uint32_t)(b_ch * 16);
#pragma unroll
            for (int np = 0; np < 4; ++np) {
                int bn = wn * 64 + np * 16 + b_n0;
                uint32_t bh[4], bl[4];
                LDSM_X4(bh[0], bh[1], bh[2], bh[3],
                        base + 20480 + bn * 80 + bkoff);
                LDSM_X4(bl[0], bl[1], bl[2], bl[3],
                        base + 30720 + bn * 80 + bkoff);
#pragma unroll
                for (int mt = 0; mt < 2; ++mt) {
#pragma unroll
                    for (int t = 0; t < 2; ++t) {
                        float* a4 = acc[mt][np * 2 + t];
                        MMA_BF16(a4, ah[mt], bh[2 * t], bh[2 * t + 1]);
                        MMA_BF16(a4, ah[mt], bl[2 * t], bl[2 * t + 1]);
                        MMA_BF16(a4, al[mt], bh[2 * t], bh[2 * t + 1]);
                    }
                }
            }
        }
        __syncthreads();
    }
#undef ISSUE_STAGE

    // ---- epilogue (identical to R11) ----
    const int lr = lane >> 2;
    const int lc = (lane & 3) * 2;
#pragma unroll
    for (int mt = 0; mt < 2; ++mt) {
#pragma unroll
        for (int g = 0; g < 8; ++g) {
            int col = wn * 64 + g * 8 + lc;
            float2 bv = *(const float2*)&bias[col];
#pragma unroll
            for (int half = 0; half < 2; ++half) {
                int r = bm + wm * 32 + mt * 16 + lr + half * 8;
                if (r >= M) continue;
                float z0 = acc[mt][g][2 * half + 0] + bv.x;
                float z1 = acc[mt][g][2 * half + 1] + bv.y;
                if (RELU) { z0 = fmaxf(z0, 0.f); z1 = fmaxf(z1, 0.f); }
                if (COMBINE) {
                    const float* rrow = res + (size_t)r * 256;
                    float2 hx = *(const float2*)&rrow[col];
                    float2 ha = *(const float2*)&rrow[128 + col];
                    z0 = fmaxf(fmaxf(z0, 0.f) + hx.x + ha.x, 0.f);
                    z1 = fmaxf(fmaxf(z1, 0.f) + hx.y + ha.y, 0.f);
                }
                if (WF32)
                    *(float2*)&Cf[(size_t)r * ldc + coff + col] = make_float2(z0, z1);
                if (WBF) {
                    __nv_bfloat16 h0, l0, h1, l1;
                    bsplit(z0, h0, l0);
                    bsplit(z1, h1, l1);
                    size_t o = (size_t)r * ldcb + coff + col;
                    *(uint32_t*)(Cbh + o) = pack_bf2(h0, h1);
                    *(uint32_t*)(Cbl + o) = pack_bf2(l0, l1);
                }
            }
        }
    }
}

// ---------------------------------------------------------------------------
// Tensor-MMA classifier (R11, proven): out[M,40] = hid @ wc + bc (padded 64).
__global__ __launch_bounds__(256, 2)
void mma_out(const float* __restrict__ A,
             const __nv_bfloat16* __restrict__ Bh,
             const __nv_bfloat16* __restrict__ Bl,
             const float* __restrict__ bias,
             float* __restrict__ out, int M) {
    __shared__ __align__(16) __nv_bfloat16 AH[128 * 24];
    __shared__ __align__(16) __nv_bfloat16 AL[128 * 24];
    __shared__ __align__(16) __nv_bfloat16 BHs[64 * 24];
    __shared__ __align__(16) __nv_bfloat16 BLs[64 * 24];

    const int tid  = threadIdx.x;
    const int wid  = tid >> 5;
    const int lane = tid & 31;
    const int bm   = blockIdx.x * 128;

    const uint32_t uAH = smem_u32(AH);
    const uint32_t uAL = smem_u32(AL);
    const uint32_t uBH = smem_u32(BHs);
    const uint32_t uBL = smem_u32(BLs);

    float acc[8][4];
#pragma unroll
    for (int j = 0; j < 8; ++j)
#pragma unroll
        for (int q = 0; q < 4; ++q) acc[j][q] = 0.f;

    const int a_r0 = (lane & 7) + ((lane >> 3) & 1) * 8;
    const int a_ch = lane >> 4;
    const int b_n0 = (lane & 7) + ((lane >> 4) & 1) * 8;
    const int b_ch = (lane >> 3) & 1;
    const int srow = tid >> 1;
    const int sh   = tid & 1;

    for (int c = 0; c < 8; ++c) {
        const int k0 = c * 16;
        {
            int gr = bm + srow;
            float4 v0 = make_float4(0.f, 0.f, 0.f, 0.f), v1 = v0;
            if (gr < M) {
                const float* p = A + (size_t)gr * 128 + k0 + sh * 8;
                v0 = *(const float4*)p;
                v1 = *(const float4*)(p + 4);
            }
            __nv_bfloat16 h0,h1,h2,h3,h4,h5,h6,h7, l0,l1,l2,l3,l4,l5,l6,l7;
            bsplit(v0.x, h0, l0); bsplit(v0.y, h1, l1);
            bsplit(v0.z, h2, l2); bsplit(v0.w, h3, l3);
            bsplit(v1.x, h4, l4); bsplit(v1.y, h5, l5);
            bsplit(v1.z, h6, l6); bsplit(v1.w, h7, l7);
            *(uint4*)&AH[srow * 24 + sh * 8] =
                make_uint4(pack_bf2(h0,h1), pack_bf2(h2,h3),
                           pack_bf2(h4,h5), pack_bf2(h6,h7));
            *(uint4*)&AL[srow * 24 + sh * 8] =
                make_uint4(pack_bf2(l0,l1), pack_bf2(l2,l3),
                           pack_bf2(l4,l5), pack_bf2(l6,l7));
        }
        if (tid < 128) {
            *(uint4*)&BHs[srow * 24 + sh * 8] =
                *(const uint4*)&Bh[(size_t)srow * 128 + k0 + sh * 8];
            *(uint4*)&BLs[srow * 24 + sh * 8] =
                *(const uint4*)&Bl[(size_t)srow * 128 + k0 + sh * 8];
        }
        __syncthreads();

        uint32_t ah[4], al[4];
        int arow = wid * 16 + a_r0;
        LDSM_X4(ah[0], ah[1], ah[2], ah[3], uAH + arow * 48 + a_ch * 16);
        LDSM_X4(al[0], al[1], al[2], al[3], uAL + arow * 48 + a_ch * 16);
#pragma unroll
        for (int np = 0; np < 4; ++np) {
            int bn = np * 16 + b_n0;
            uint32_t bh[4], bl[4];
            LDSM_X4(bh[0], bh[1], bh[2], bh[3], uBH + bn * 48 + b_ch * 16);
            LDSM_X4(bl[0], bl[1], bl[2], bl[3], uBL + bn * 48 + b_ch * 16);
#pragma unroll
            for (int t = 0; t < 2; ++t) {
                float* a4 = acc[np * 2 + t];
                MMA_BF16(a4, ah, bh[2 * t], bh[2 * t + 1]);
                MMA_BF16(a4, ah, bl[2 * t], bl[2 * t + 1]);
                MMA_BF16(a4, al, bh[2 * t], bh[2 * t + 1]);
            }
        }
        __syncthreads();
    }

    const int lr = lane >> 2;
    const int lc = (lane & 3) * 2;
#pragma unroll
    for (int g = 0; g < 8; ++g) {
        int col = g * 8 + lc;
        if (col >= 40) continue;
        float2 bv = *(const float2*)&bias[col];
#pragma unroll
        for (int half = 0; half < 2; ++half) {
            int r = bm + wid * 16 + lr + half * 8;
            if (r >= M) continue;
            float z0 = acc[g][2 * half + 0] + bv.x;
            float z1 = acc[g][2 * half + 1] + bv.y;
            *(float2*)&out[(size_t)r * 40 + col] = make_float2(z0, z1);
        }
    }
}

// ---------------------------------------------------------------------------
extern "C" void kernel_launch(void* const* d_in, const int* in_sizes, int n_in,
                              void* d_out, int out_size) {
    const float* x   = (const float*)d_in[0];
    const int*   ei  = (const int*)  d_in[1];
    const float* emb = (const float*)d_in[2];
    const float* wx1 = (const float*)d_in[3];
    const float* bx1 = (const float*)d_in[4];
    const float* wx2 = (const float*)d_in[5];
    const float* bx2 = (const float*)d_in[6];
    const float* wa1 = (const float*)d_in[7];
    const float* ba1 = (const float*)d_in[8];
    const float* wa2 = (const float*)d_in[9];
    const float* ba2 = (const float*)d_in[10];
    const float* ww1 = (const float*)d_in[11];
    const float* bw1 = (const float*)d_in[12];
    const float* wc  = (const float*)d_in[13];
    const float* bc  = (const float*)d_in[14];
    float* out = (float*)d_out;

    const int M = in_sizes[0] / INDIM;   // 100000
    const int E = in_sizes[1] / 2;       // 1600000

    float *hid, *cat;
    __nv_bfloat16 *wt, *xs, *hb, *h2b, *aggb, *catb;
    int *cnt, *cur, *off, *bins;
    cudaGetSymbolAddress((void**)&hid,  g_hid);
    cudaGetSymbolAddress((void**)&cat,  g_cat);
    cudaGetSymbolAddress((void**)&wt,   g_wt);
    cudaGetSymbolAddress((void**)&xs,   g_xs);
    cudaGetSymbolAddress((void**)&hb,   g_hb);
    cudaGetSymbolAddress((void**)&h2b,  g_h2b);
    cudaGetSymbolAddress((void**)&aggb, g_aggb);
    cudaGetSymbolAddress((void**)&catb, g_catb);
    cudaGetSymbolAddress((void**)&cnt,  g_cnt);
    cudaGetSymbolAddress((void**)&cur,  g_cur);
    cudaGetSymbolAddress((void**)&off,  g_off);
    cudaGetSymbolAddress((void**)&bins, g_bins);

    __nv_bfloat16 *xsh = xs,   *xsl = xs   + (size_t)M * INDIM;
    __nv_bfloat16 *hbh = hb,   *hbl = hb   + (size_t)M * HID;
    __nv_bfloat16 *h2h = h2b,  *h2l = h2b  + (size_t)M * HID;
    __nv_bfloat16 *agh = aggb, *agl = aggb + (size_t)M * HID;
    __nv_bfloat16 *cbh = catb, *cbl = catb + (size_t)M * 2 * HID;
    __nv_bfloat16 *W1h = wt,           *W1l = wt + 32768;
    __nv_bfloat16 *W2h = wt + 65536,   *W2l = wt + 81920;
    __nv_bfloat16 *W3h = wt + 98304,   *W3l = wt + 114688;
    __nv_bfloat16 *W4h = wt + 131072,  *W4l = wt + 147456;
    __nv_bfloat16 *W5h = wt + 163840,  *W5l = wt + 196608;
    __nv_bfloat16 *W6h = wt + 229376,  *W6l = wt + 237568;

    static cudaStream_t s_side = nullptr;
    static cudaEvent_t  ev_fork = nullptr, ev_prep = nullptr, ev_join = nullptr;
    if (s_side == nullptr) {
        cudaStreamCreateWithFlags(&s_side, cudaStreamNonBlocking);
        cudaEventCreateWithFlags(&ev_fork, cudaEventDisableTiming);
        cudaEventCreateWithFlags(&ev_prep, cudaEventDisableTiming);
        cudaEventCreateWithFlags(&ev_join, cudaEventDisableTiming);
        const int SM = 81920;
        cudaFuncSetAttribute(mma_gemm3<INDIM, 1, 1, 0, 0>,
                             cudaFuncAttributeMaxDynamicSharedMemorySize, SM);
        cudaFuncSetAttribute(mma_gemm3<HID, 0, 1, 1, 0>,
                             cudaFuncAttributeMaxDynamicSharedMemorySize, SM);
        cudaFuncSetAttribute(mma_gemm3<HID, 1, 1, 0, 0>,
                             cudaFuncAttributeMaxDynamicSharedMemorySize, SM);
        cudaFuncSetAttribute(mma_gemm3<2 * HID, 0, 0, 1, 1>,
                             cudaFuncAttributeMaxDynamicSharedMemorySize, SM);
    }

    const int gb = (M + 127) / 128;   // 782
    const int SMB = 81920;

    // ---- fork ----
    cudaEventRecord(ev_fork, 0);
    cudaStreamWaitEvent(s_side, ev_fork, 0);

    // side: binning + gather -> aggb planes
    zero_cnt<<<(M + 255) / 256, 256, 0, s_side>>>(cnt, cur, M);
    count_kernel<<<1184, 256, 0, s_side>>>(ei, cnt, E);
    scan_kernel<<<1, 1024, 0, s_side>>>(cnt, off, M);
    fill_kernel<<<1184, 256, 0, s_side>>>(ei, off, cur, bins, E);
    gather_kernel<<<(M * 32 + 255) / 256, 256, 0, s_side>>>(off, bins, emb, agh, agl, M);

    // main: preps
    prep_all<<<(114688 + 255) / 256, 256>>>(wx1, wx2, wa1, wa2, ww1, wt);
    prep_wc<<<(8192 + 255) / 256, 256>>>(wc, wt);
    const int n4x = M * (INDIM / 4);
    prep_x<<<(n4x + 255) / 256, 256>>>((const float4*)x, xsh, xsl, n4x);
    cudaEventRecord(ev_prep, 0);

    // side continues: G3 then G4
    cudaStreamWaitEvent(s_side, ev_prep, 0);
    mma_gemm3<HID, 1, 1, 0, 0><<<gb, 256, SMB, s_side>>>(agh, agl, W3h, W3l, ba1,
                                                         h2h, h2l, HID, nullptr, nullptr, 0, 0, M);
    mma_gemm3<HID, 0, 1, 1, 0><<<gb, 256, SMB, s_side>>>(h2h, h2l, W4h, W4l, ba2,
                                                         cbh, cbl, 256, cat, nullptr, 256, 128, M);
    cudaEventRecord(ev_join, s_side);

    // main: G1, G2
    mma_gemm3<INDIM, 1, 1, 0, 0><<<gb, 256, SMB>>>(xsh, xsl, W1h, W1l, bx1,
                                                   hbh, hbl, HID, nullptr, nullptr, 0, 0, M);
    mma_gemm3<HID, 0, 1, 1, 0><<<gb, 256, SMB>>>(hbh, hbl, W2h, W2l, bx2,
                                                 cbh, cbl, 256, cat, nullptr, 256, 0, M);

    // ---- join ----
    cudaStreamWaitEvent(0, ev_join, 0);

    // G5: hid = relu(relu(catb @ ww1 + bw1) + hx + ha)
    mma_gemm3<2 * HID, 0, 0, 1, 1><<<gb, 256, SMB>>>(cbh, cbl, W5h, W5l, bw1,
                                                     nullptr, nullptr, 0, hid, cat, 128, 0, M);
    // G6
    mma_out<<<gb, 256>>>(hid, W6h, W6l, bc, out, M);
}